// round 2
// baseline (speedup 1.0000x reference)
#include <cuda_runtime.h>
#include <math.h>

#define HH 192
#define WW 192
#define OH 182
#define OW 182
#define OHW (OH*OW)
#define NB 8
#define NC 64
#define NF 3

#define SSIM_C1 0.01f
#define SSIM_C2 0.09f

// 11-tap gaussian (sigma=1.5), normalized; literals so every blur FMA is
// FFMA with immediate multiplier (rt_SMSP = 1 on sm_10x).
#define GW0 0.00102838f
#define GW1 0.00759876f
#define GW2 0.03600077f
#define GW3 0.10936069f
#define GW4 0.21300554f
#define GW5 0.26601173f

#define FOREACH_TAP(M) M(0,GW0) M(1,GW1) M(2,GW2) M(3,GW3) M(4,GW4) M(5,GW5) \
                       M(6,GW4) M(7,GW3) M(8,GW2) M(9,GW1) M(10,GW0)

// __device__ scratch (allocation-free rule)
__device__ float g_muf [NB*NF*OH*OW];
__device__ float g_sigf[NB*NF*OH*OW];
__device__ float g_ssim[NB*NF*NC];

// ---------------------------------------------------------------------------
// Kernel 1: per-(b,f) gaussian moments mu_f, sig_f. Grid (8 strips, 24 ch).
// ---------------------------------------------------------------------------
__global__ void __launch_bounds__(192) f_moments_kernel(const float* __restrict__ f)
{
    const int s   = blockIdx.x;          // row strip 0..7 (23 output rows each)
    const int bj  = blockIdx.y;          // 0..23  (b*3+j)
    const int tid = threadIdx.x;         // 0..191
    const float* fp = f + (size_t)bj * HH * WW;
    const int o0   = s * 23;
    const int o1   = min(OH, o0 + 23);   // exclusive
    const int rend = o1 + 9;             // last input row (inclusive)

    __shared__ float2 sp[2][192];
    float a0[11], a1[11];
#pragma unroll
    for (int i = 0; i < 11; ++i) { a0[i] = 0.f; a1[i] = 0.f; }

    float fv = fp[o0 * WW + tid];
    for (int r = o0; r <= rend; ++r) {
        const int buf = r & 1;
        sp[buf][tid] = make_float2(fv, fv * fv);
        float nfv = 0.f;
        if (r < rend) nfv = fp[(r + 1) * WW + tid];
        __syncthreads();
        if (tid < OW) {
            const float2* spb = sp[buf];
            float h0 = 0.f, h1 = 0.f;
#define K1H(k, GK) { float2 q = spb[tid + (k)]; h0 = fmaf((GK), q.x, h0); h1 = fmaf((GK), q.y, h1); }
            FOREACH_TAP(K1H)
#undef K1H
#pragma unroll
            for (int j = 10; j >= 1; --j) { a0[j] = a0[j-1]; a1[j] = a1[j-1]; }
            a0[0] = 0.f; a1[0] = 0.f;
#define K1A(j, GJ) { a0[j] = fmaf((GJ), h0, a0[j]); a1[j] = fmaf((GJ), h1, a1[j]); }
            FOREACH_TAP(K1A)
#undef K1A
            if (r - 10 >= o0) {
                const int o = r - 10;
                const float mu = a0[10];
                const int idx = bj * OHW + o * OW + tid;
                g_muf[idx]  = mu;
                g_sigf[idx] = a1[10] - mu * mu;
            }
        }
        fv = nfv;
    }
}

// ---------------------------------------------------------------------------
// Kernel 2: main SSIM. One block per (b,c). 192 threads, thread = out column.
// 5 fields blurred: x, x^2, f0*x, f1*x, f2*x. Vertical blur via 11-slot
// register ring, phase-unrolled so all indices/weights are compile-time.
// ---------------------------------------------------------------------------

// ring slot for output row (r - t), given r = rbase + PH, rbase % 11 == 0
#define RS(PH,t) (((PH) + 22 - (t)) % 11)

#define HT(t,G) { float4 q4 = s4[tid+(t)]; float q1 = s1[tid+(t)]; \
    h0=fmaf((G),q4.x,h0); h1=fmaf((G),q4.y,h1); h2=fmaf((G),q4.z,h2); \
    h3=fmaf((G),q4.w,h3); h4=fmaf((G),q1,h4); }

#define VT(PH,t,G) { a0[RS(PH,t)]=fmaf((G),h0,a0[RS(PH,t)]); \
    a1[RS(PH,t)]=fmaf((G),h1,a1[RS(PH,t)]); \
    a2[RS(PH,t)]=fmaf((G),h2,a2[RS(PH,t)]); \
    a3[RS(PH,t)]=fmaf((G),h3,a3[RS(PH,t)]); \
    a4[RS(PH,t)]=fmaf((G),h4,a4[RS(PH,t)]); }

#define VTG(PH,t,G) { if ((PH) >= (t)) VT(PH,t,G) }   // warm-up guard, folded

#define VACC(PH)  VT(PH,0,GW0)  VT(PH,1,GW1)  VT(PH,2,GW2)  VT(PH,3,GW3) \
                  VT(PH,4,GW4)  VT(PH,5,GW5)  VT(PH,6,GW4)  VT(PH,7,GW3) \
                  VT(PH,8,GW2)  VT(PH,9,GW1)  VT(PH,10,GW0)
#define VACCG(PH) VTG(PH,0,GW0) VTG(PH,1,GW1) VTG(PH,2,GW2) VTG(PH,3,GW3) \
                  VTG(PH,4,GW4) VTG(PH,5,GW5) VTG(PH,6,GW4) VTG(PH,7,GW3) \
                  VTG(PH,8,GW2) VTG(PH,9,GW1) VTG(PH,10,GW0)

#define SSIM_J(MUF, SGF, AX) { \
    float cr  = (AX) - (MUF)*mux; \
    float num = (2.f*(MUF)*mux + SSIM_C1)*(2.f*cr + SSIM_C2); \
    float den = ((MUF)*(MUF) + mux2 + SSIM_C1)*((SGF) + c2s); \
    /* accumulate */ \
    _sacc += __fdividef(num, den); }

#define ROW(PH, VM, EGUARD) { \
    const int r = rbase + (PH); \
    if (r < HH) { \
        const int buf = r & 1; \
        sp4[buf][tid] = make_float4(cx, cx*cx, cf0*cx, cf1*cx); \
        sp1[buf][tid] = cf2*cx; \
        if (r + 1 < HH) { \
            const int nofs = (r+1)*WW + tid; \
            nx = xp[nofs]; nf0 = fq0[nofs]; nf1 = fq1[nofs]; nf2 = fq2[nofs]; \
        } \
        __syncthreads(); \
        if (tid < OW) { \
            const bool em = (EGUARD); \
            float muf0=0.f,muf1=0.f,muf2=0.f,sgf0=0.f,sgf1=0.f,sgf2=0.f; \
            if (em) { \
                const int base = (r-10)*OW + tid; \
                muf0 = g_muf[mb0+base]; sgf0 = g_sigf[mb0+base]; \
                muf1 = g_muf[mb1+base]; sgf1 = g_sigf[mb1+base]; \
                muf2 = g_muf[mb2+base]; sgf2 = g_sigf[mb2+base]; \
            } \
            float h0=0.f,h1=0.f,h2=0.f,h3=0.f,h4=0.f; \
            const float4* s4 = sp4[buf]; const float* s1 = sp1[buf]; \
            HT(0,GW0) HT(1,GW1) HT(2,GW2) HT(3,GW3) HT(4,GW4) HT(5,GW5) \
            HT(6,GW4) HT(7,GW3) HT(8,GW2) HT(9,GW1) HT(10,GW0) \
            VM(PH) \
            if (em) { \
                const int e = (((PH)+1) % 11); \
                float mux  = a0[e]; \
                float mux2 = mux*mux; \
                float sx   = a1[e] - mux2; \
                float c2s  = sx + SSIM_C2; \
                { float _sacc = ssum0; SSIM_J(muf0, sgf0, a2[e]) ssum0 = _sacc; } \
                { float _sacc = ssum1; SSIM_J(muf1, sgf1, a3[e]) ssum1 = _sacc; } \
                { float _sacc = ssum2; SSIM_J(muf2, sgf2, a4[e]) ssum2 = _sacc; } \
                a0[e]=0.f; a1[e]=0.f; a2[e]=0.f; a3[e]=0.f; a4[e]=0.f; \
            } \
        } \
        cx = nx; cf0 = nf0; cf1 = nf1; cf2 = nf2; \
    } }

__global__ void __launch_bounds__(192) ssim_main_kernel(
    const float* __restrict__ x, const float* __restrict__ f,
    float* __restrict__ out, int out_size)
{
    const int bc  = blockIdx.x;          // b*64 + c
    const int b   = bc >> 6;
    const int c   = bc & 63;
    const int tid = threadIdx.x;

    const float* xp  = x + (size_t)bc * HH * WW;
    const float* fq0 = f + (size_t)(b*3 + 0) * HH * WW;
    const float* fq1 = f + (size_t)(b*3 + 1) * HH * WW;
    const float* fq2 = f + (size_t)(b*3 + 2) * HH * WW;
    const int mb0 = (b*3 + 0) * OHW;
    const int mb1 = (b*3 + 1) * OHW;
    const int mb2 = (b*3 + 2) * OHW;

    __shared__ float4 sp4[2][192];
    __shared__ float  sp1[2][192];
    __shared__ float  wred[3][6];

    float a0[11], a1[11], a2[11], a3[11], a4[11];
#pragma unroll
    for (int i = 0; i < 11; ++i) { a0[i]=0.f; a1[i]=0.f; a2[i]=0.f; a3[i]=0.f; a4[i]=0.f; }
    float ssum0 = 0.f, ssum1 = 0.f, ssum2 = 0.f;

    // prologue: preload row 0
    float cx = xp[tid], cf0 = fq0[tid], cf1 = fq1[tid], cf2 = fq2[tid];
    float nx = 0.f, nf0 = 0.f, nf1 = 0.f, nf2 = 0.f;

    {   // first 11 rows: warm-up (compile-time pruned guards)
        const int rbase = 0;
        ROW(0,  VACCG, false) ROW(1,  VACCG, false) ROW(2,  VACCG, false)
        ROW(3,  VACCG, false) ROW(4,  VACCG, false) ROW(5,  VACCG, false)
        ROW(6,  VACCG, false) ROW(7,  VACCG, false) ROW(8,  VACCG, false)
        ROW(9,  VACCG, false) ROW(10, VACCG, true)
    }
    for (int rbase = 11; rbase < HH; rbase += 11) {
        ROW(0,  VACC, true) ROW(1,  VACC, true) ROW(2,  VACC, true)
        ROW(3,  VACC, true) ROW(4,  VACC, true) ROW(5,  VACC, true)
        ROW(6,  VACC, true) ROW(7,  VACC, true) ROW(8,  VACC, true)
        ROW(9,  VACC, true) ROW(10, VACC, true)
    }

    // block reduction of the 3 per-thread sums (tid>=182 hold zeros)
    __syncthreads();
    float v0 = ssum0, v1 = ssum1, v2 = ssum2;
#pragma unroll
    for (int off = 16; off; off >>= 1) {
        v0 += __shfl_down_sync(0xFFFFFFFFu, v0, off);
        v1 += __shfl_down_sync(0xFFFFFFFFu, v1, off);
        v2 += __shfl_down_sync(0xFFFFFFFFu, v2, off);
    }
    const int wid = tid >> 5, lane = tid & 31;
    if (lane == 0) { wred[0][wid] = v0; wred[1][wid] = v1; wred[2][wid] = v2; }
    __syncthreads();
    if (tid == 0) {
        float s0 = 0.f, s1 = 0.f, s2 = 0.f;
#pragma unroll
        for (int w = 0; w < 6; ++w) { s0 += wred[0][w]; s1 += wred[1][w]; s2 += wred[2][w]; }
        const float inv = 1.0f / (float)(OH * OW);
        s0 *= inv; s1 *= inv; s2 *= inv;
        g_ssim[(b*3 + 0)*NC + c] = s0;
        g_ssim[(b*3 + 1)*NC + c] = s1;
        g_ssim[(b*3 + 2)*NC + c] = s2;
        if (out_size >= 2048) {
            out[512 + b*NF*NC + 0*NC + c] = s0;
            out[512 + b*NF*NC + 1*NC + c] = s1;
            out[512 + b*NF*NC + 2*NC + c] = s2;
        }
    }
}

// ---------------------------------------------------------------------------
// Kernel 3: spatial gate conv (3,1) over C, relu, MLP 64->64->64, sigmoid.
// Grid 8 (per b), 64 threads (per c).
// ---------------------------------------------------------------------------
__global__ void __launch_bounds__(64) epilogue_kernel(
    const float* __restrict__ sw,
    const float* __restrict__ W1, const float* __restrict__ b1,
    const float* __restrict__ W2, const float* __restrict__ b2,
    float* __restrict__ out)
{
    const int b = blockIdx.x;
    const int c = threadIdx.x;

    __shared__ float ss[3][66];     // zero-padded ssim_info for this b
    __shared__ float gate[64];
    __shared__ float h1s[64];

#pragma unroll
    for (int j = 0; j < 3; ++j) {
        ss[j][c + 1] = g_ssim[(b*3 + j)*NC + c];
        if (c == 0)  ss[j][0]  = 0.f;
        if (c == 63) ss[j][65] = 0.f;
    }
    __syncthreads();

    float g = 0.f;
#pragma unroll
    for (int j = 0; j < 3; ++j)
#pragma unroll
        for (int d = 0; d < 3; ++d)
            g = fmaf(sw[j*3 + d], ss[j][c + d], g);
    gate[c] = fmaxf(g, 0.f);
    __syncthreads();

    float h1 = b1[c];
#pragma unroll 8
    for (int k = 0; k < 64; ++k) h1 = fmaf(W1[c*64 + k], gate[k], h1);
    h1s[c] = fmaxf(h1, 0.f);
    __syncthreads();

    float h2 = b2[c];
#pragma unroll 8
    for (int k = 0; k < 64; ++k) h2 = fmaf(W2[c*64 + k], h1s[k], h2);
    out[b*64 + c] = 1.0f / (1.0f + expf(-h2));
}

// ---------------------------------------------------------------------------
extern "C" void kernel_launch(void* const* d_in, const int* in_sizes, int n_in,
                              void* d_out, int out_size)
{
    const float* x  = (const float*)d_in[0];
    const float* f  = (const float*)d_in[1];
    const float* sw = (const float*)d_in[2];
    const float* W1 = (const float*)d_in[3];
    const float* b1 = (const float*)d_in[4];
    const float* W2 = (const float*)d_in[5];
    const float* b2 = (const float*)d_in[6];
    float* out = (float*)d_out;

    f_moments_kernel<<<dim3(8, 24), 192>>>(f);
    ssim_main_kernel<<<NB*NC, 192>>>(x, f, out, out_size);
    epilogue_kernel<<<NB, 64>>>(sw, W1, b1, W2, b2, out);
}

// round 4
// speedup vs baseline: 1.2508x; 1.2508x over previous
#include <cuda_runtime.h>
#include <math.h>

#define HH 192
#define WW 192
#define OH 182
#define OW 182
#define OHW (OH*OW)
#define NB 8
#define NC 64
#define NF 3

#define SSIM_C1 0.01f
#define SSIM_C2 0.09f

// 11-tap gaussian (sigma=1.5), normalized; literals so blur FMAs compile to
// FFMA with immediate multiplier (rt_SMSP = 1 on sm_10x).
#define GW0 0.00102838f
#define GW1 0.00759876f
#define GW2 0.03600077f
#define GW3 0.10936069f
#define GW4 0.21300554f
#define GW5 0.26601173f

// __device__ scratch (allocation-free rule)
__device__ float g_muf [NB*NF*OH*OW];
__device__ float g_sigf[NB*NF*OH*OW];
__device__ float g_ssim[NB*NF*NC];

// ---------------------------------------------------------------------------
// Kernel 0: zero the ssim accumulator (atomicAdd target; must reset per launch)
// ---------------------------------------------------------------------------
__global__ void zero_ssim_kernel()
{
    int i = blockIdx.x * blockDim.x + threadIdx.x;
    if (i < NB*NF*NC) g_ssim[i] = 0.f;
}

// ---------------------------------------------------------------------------
// Kernel 1: per-(b,f) gaussian moments mu_f, sig_f. Grid (14 strips, 24 ch).
// ---------------------------------------------------------------------------
__global__ void __launch_bounds__(192) f_moments_kernel(const float* __restrict__ f)
{
    const int s   = blockIdx.x;          // row strip 0..13 (13 output rows each)
    const int bj  = blockIdx.y;          // 0..23  (b*3+j)
    const int tid = threadIdx.x;         // 0..191
    const float* fp = f + (size_t)bj * HH * WW;
    const int o0   = s * 13;
    const int o1   = min(OH, o0 + 13);   // exclusive
    const int rend = o1 + 9;             // last input row (inclusive)

    __shared__ float2 sp[2][192];
    float a0[11], a1[11];
#pragma unroll
    for (int i = 0; i < 11; ++i) { a0[i] = 0.f; a1[i] = 0.f; }

#define FOREACH_TAP(M) M(0,GW0) M(1,GW1) M(2,GW2) M(3,GW3) M(4,GW4) M(5,GW5) \
                       M(6,GW4) M(7,GW3) M(8,GW2) M(9,GW1) M(10,GW0)

    float fv = fp[o0 * WW + tid];
    for (int r = o0; r <= rend; ++r) {
        const int buf = r & 1;
        sp[buf][tid] = make_float2(fv, fv * fv);
        float nfv = 0.f;
        if (r < rend) nfv = fp[(r + 1) * WW + tid];
        __syncthreads();
        if (tid < OW) {
            const float2* spb = sp[buf];
            float h0 = 0.f, h1 = 0.f;
#define K1H(k, GK) { float2 q = spb[tid + (k)]; h0 = fmaf((GK), q.x, h0); h1 = fmaf((GK), q.y, h1); }
            FOREACH_TAP(K1H)
#undef K1H
#pragma unroll
            for (int j = 10; j >= 1; --j) { a0[j] = a0[j-1]; a1[j] = a1[j-1]; }
            a0[0] = 0.f; a1[0] = 0.f;
#define K1A(j, GJ) { a0[j] = fmaf((GJ), h0, a0[j]); a1[j] = fmaf((GJ), h1, a1[j]); }
            FOREACH_TAP(K1A)
#undef K1A
            if (r - 10 >= o0) {
                const int o = r - 10;
                const float mu = a0[10];
                const int idx = bj * OHW + o * OW + tid;
                g_muf[idx]  = mu;
                g_sigf[idx] = a1[10] - mu * mu;
            }
        }
        fv = nfv;
    }
}

// ---------------------------------------------------------------------------
// Kernel 2: main SSIM, warp-specialized two-team version.
// Grid (512, 2): blockIdx.x = b*64+c, blockIdx.y = row half (91 out rows).
// 384 threads: team X (tid<192) blurs {x, x^2}; team F blurs {f_j*x} and
// computes SSIM using the {mu_x, sig_x} exchange from the PREVIOUS row, so
// only one __syncthreads per row is needed. Ring registers are overlaid
// between teams to keep pressure low.
// ---------------------------------------------------------------------------

// ring slot for output row (q - t), q = within-strip phase, PH = q mod 11
#define RS(PH,t) (((PH) + 22 - (t)) % 11)

#define HTX(t,G) { float2 q = bx2[c + (t)]; \
    h0 = fmaf((G), q.x, h0); h1 = fmaf((G), q.y, h1); }

#define HTF(t,G) { float2 q = bf01[c + (t)]; float q2 = bf2[c + (t)]; \
    h2 = fmaf((G), q.x, h2); h3 = fmaf((G), q.y, h3); h4 = fmaf((G), q2, h4); }

#define VTX(PH,t,G,WARMF) { if (!(WARMF) || (PH) >= (t)) { \
    rA[RS(PH,t)] = fmaf((G), h0, rA[RS(PH,t)]); \
    rB[RS(PH,t)] = fmaf((G), h1, rB[RS(PH,t)]); } }

#define VTF(PH,t,G,WARMF) { if (!(WARMF) || (PH) >= (t)) { \
    rA[RS(PH,t)] = fmaf((G), h2, rA[RS(PH,t)]); \
    rB[RS(PH,t)] = fmaf((G), h3, rB[RS(PH,t)]); \
    rD[RS(PH,t)] = fmaf((G), h4, rD[RS(PH,t)]); } }

#define VX(PH,W) VTX(PH,0,GW0,W) VTX(PH,1,GW1,W) VTX(PH,2,GW2,W) VTX(PH,3,GW3,W) \
                 VTX(PH,4,GW4,W) VTX(PH,5,GW5,W) VTX(PH,6,GW4,W) VTX(PH,7,GW3,W) \
                 VTX(PH,8,GW2,W) VTX(PH,9,GW1,W) VTX(PH,10,GW0,W)
#define VF(PH,W) VTF(PH,0,GW0,W) VTF(PH,1,GW1,W) VTF(PH,2,GW2,W) VTF(PH,3,GW3,W) \
                 VTF(PH,4,GW4,W) VTF(PH,5,GW5,W) VTF(PH,6,GW4,W) VTF(PH,7,GW3,W) \
                 VTF(PH,8,GW2,W) VTF(PH,9,GW1,W) VTF(PH,10,GW0,W)

#define SSJ(MU,SG,P,S) { \
    const float mm  = (MU) * mux; \
    const float num = (2.f*mm + SSIM_C1) * (2.f*((P) - mm) + SSIM_C2); \
    const float den = (fmaf((MU),(MU),mux2) + SSIM_C1) * ((SG) + c2s); \
    S += __fdividef(num, den); }

#define ROW(PH, WARMF) { \
    const int r = rbase + (PH); \
    if (r < rend) { \
        const int buf = r & 1; \
        if (isX) { \
            sx2[buf][c] = make_float2(v0, v0*v0); \
            n0 = 0.f; \
            if (r + 1 < rend) n0 = xp[(r+1)*WW + c]; \
        } else { \
            sf01[buf][c] = make_float2(v1*v0, v2*v0); \
            sf2 [buf][c] = v3*v0; \
            n0 = 0.f; n1 = 0.f; n2 = 0.f; n3 = 0.f; \
            if (r + 1 < rend) { const int no = (r+1)*WW + c; \
                n0 = xp[no]; n1 = fq0[no]; n2 = fq1[no]; n3 = fq2[no]; } \
            if ((!(WARMF) || (PH) >= 10) && c < OW) { \
                const int mbase = (r-10)*OW + c; \
                nmu0 = g_muf[mb0+mbase]; nsg0 = g_sigf[mb0+mbase]; \
                nmu1 = g_muf[mb1+mbase]; nsg1 = g_sigf[mb1+mbase]; \
                nmu2 = g_muf[mb2+mbase]; nsg2 = g_sigf[mb2+mbase]; } \
        } \
        __syncthreads(); \
        if (c < OW) { \
            if (isX) { \
                float h0 = 0.f, h1 = 0.f; \
                const float2* bx2 = sx2[buf]; \
                HTX(0,GW0) HTX(1,GW1) HTX(2,GW2) HTX(3,GW3) HTX(4,GW4) HTX(5,GW5) \
                HTX(6,GW4) HTX(7,GW3) HTX(8,GW2) HTX(9,GW1) HTX(10,GW0) \
                VX(PH, WARMF) \
                if (!(WARMF) || (PH) == 10) { \
                    const int e = ((PH)+1) % 11; \
                    const float mux = rA[e]; \
                    sex[buf][c] = make_float2(mux, rB[e] - mux*mux); \
                    rA[e] = 0.f; rB[e] = 0.f; } \
            } else { \
                float h2 = 0.f, h3 = 0.f, h4 = 0.f; \
                const float2* bf01 = sf01[buf]; const float* bf2 = sf2[buf]; \
                HTF(0,GW0) HTF(1,GW1) HTF(2,GW2) HTF(3,GW3) HTF(4,GW4) HTF(5,GW5) \
                HTF(6,GW4) HTF(7,GW3) HTF(8,GW2) HTF(9,GW1) HTF(10,GW0) \
                VF(PH, WARMF) \
                if (!(WARMF)) { \
                    const float2 ex = sex[buf ^ 1][c]; \
                    const float mux = ex.x, mux2 = ex.x*ex.x, c2s = ex.y + SSIM_C2; \
                    SSJ(mu0, sg0, p0, s0) \
                    SSJ(mu1, sg1, p1, s1) \
                    SSJ(mu2, sg2, p2, s2) } \
                if (!(WARMF) || (PH) == 10) { \
                    const int e = ((PH)+1) % 11; \
                    p0 = rA[e]; p1 = rB[e]; p2 = rD[e]; \
                    rA[e] = 0.f; rB[e] = 0.f; rD[e] = 0.f; \
                    mu0 = nmu0; sg0 = nsg0; mu1 = nmu1; sg1 = nsg1; mu2 = nmu2; sg2 = nsg2; } \
            } \
        } \
        if (isX) { v0 = n0; } else { v0 = n0; v1 = n1; v2 = n2; v3 = n3; } \
    } }

__global__ void __launch_bounds__(384, 2) ssim_main_kernel(
    const float* __restrict__ x, const float* __restrict__ f)
{
    const int bc  = blockIdx.x;          // b*64 + c
    const int b   = bc >> 6;
    const int ch  = bc & 63;
    const int tid = threadIdx.x;
    const bool isX = tid < 192;
    const int c   = isX ? tid : tid - 192;

    const int r0s  = blockIdx.y * 91;    // strip input start
    const int rend = r0s + 101;          // strip input end (exclusive); 91+101=192 ok

    const float* xp  = x + (size_t)bc * HH * WW;
    const float* fq0 = f + (size_t)(b*3 + 0) * HH * WW;
    const float* fq1 = f + (size_t)(b*3 + 1) * HH * WW;
    const float* fq2 = f + (size_t)(b*3 + 2) * HH * WW;
    const int mb0 = (b*3 + 0) * OHW;
    const int mb1 = (b*3 + 1) * OHW;
    const int mb2 = (b*3 + 2) * OHW;

    __shared__ float2 sx2 [2][192];
    __shared__ float2 sf01[2][192];
    __shared__ float  sf2 [2][192];
    __shared__ float2 sex [2][192];      // exchange {mu_x, sig_x}
    __shared__ float  wredF[6][3];

    // overlaid vertical rings: X uses rA,rB; F uses rA,rB,rD
    float rA[11], rB[11], rD[11];
#pragma unroll
    for (int i = 0; i < 11; ++i) { rA[i] = 0.f; rB[i] = 0.f; rD[i] = 0.f; }

    float v0 = 0.f, v1 = 0.f, v2 = 0.f, v3 = 0.f;
    float n0 = 0.f, n1 = 0.f, n2 = 0.f, n3 = 0.f;
    float p0 = 0.f, p1 = 0.f, p2 = 0.f;
    float mu0 = 0.f, mu1 = 0.f, mu2 = 0.f, sg0 = 0.f, sg1 = 0.f, sg2 = 0.f;
    float nmu0 = 0.f, nmu1 = 0.f, nmu2 = 0.f, nsg0 = 0.f, nsg1 = 0.f, nsg2 = 0.f;
    float s0 = 0.f, s1 = 0.f, s2 = 0.f;

    // preload strip first row
    if (isX) {
        v0 = xp[r0s*WW + c];
    } else {
        const int o = r0s*WW + c;
        v0 = xp[o]; v1 = fq0[o]; v2 = fq1[o]; v3 = fq2[o];
    }

    {   // warm-up 11 rows (compile-time pruned ring guards; no SSIM consume)
        const int rbase = r0s;
        ROW(0,1) ROW(1,1) ROW(2,1) ROW(3,1) ROW(4,1) ROW(5,1)
        ROW(6,1) ROW(7,1) ROW(8,1) ROW(9,1) ROW(10,1)
    }
    for (int rbase = r0s + 11; rbase < rend; rbase += 11) {
        ROW(0,0) ROW(1,0) ROW(2,0) ROW(3,0) ROW(4,0) ROW(5,0)
        ROW(6,0) ROW(7,0) ROW(8,0) ROW(9,0) ROW(10,0)
    }

    // flush: consume the last pending output row (uses sex written at rend-1)
    __syncthreads();
    if (!isX && c < OW) {
        const float2 ex = sex[(rend-1) & 1][c];
        const float mux = ex.x, mux2 = ex.x*ex.x, c2s = ex.y + SSIM_C2;
        SSJ(mu0, sg0, p0, s0)
        SSJ(mu1, sg1, p1, s1)
        SSJ(mu2, sg2, p2, s2)
    }

    // reduce the 3 sums over team F and atomically accumulate into g_ssim
    if (!isX) {
        const float inv = 1.0f / (float)(OH * OW);
        float t0 = s0 * inv, t1 = s1 * inv, t2 = s2 * inv;
#pragma unroll
        for (int off = 16; off; off >>= 1) {
            t0 += __shfl_down_sync(0xFFFFFFFFu, t0, off);
            t1 += __shfl_down_sync(0xFFFFFFFFu, t1, off);
            t2 += __shfl_down_sync(0xFFFFFFFFu, t2, off);
        }
        const int fw = (tid - 192) >> 5, lane = tid & 31;
        if (lane == 0) { wredF[fw][0] = t0; wredF[fw][1] = t1; wredF[fw][2] = t2; }
    }
    __syncthreads();
    if (tid == 192) {
        float q0 = 0.f, q1 = 0.f, q2 = 0.f;
#pragma unroll
        for (int w = 0; w < 6; ++w) { q0 += wredF[w][0]; q1 += wredF[w][1]; q2 += wredF[w][2]; }
        atomicAdd(&g_ssim[(b*3 + 0)*NC + ch], q0);
        atomicAdd(&g_ssim[(b*3 + 1)*NC + ch], q1);
        atomicAdd(&g_ssim[(b*3 + 2)*NC + ch], q2);
    }
}

// ---------------------------------------------------------------------------
// Kernel 3: emit ssim_info to out[512:2048]; spatial gate conv (3,1) over C,
// relu, MLP 64->64->64, sigmoid -> out[0:512]. Grid 8 (per b), 64 threads.
// ---------------------------------------------------------------------------
__global__ void __launch_bounds__(64) epilogue_kernel(
    const float* __restrict__ sw,
    const float* __restrict__ W1, const float* __restrict__ b1,
    const float* __restrict__ W2, const float* __restrict__ b2,
    float* __restrict__ out, int out_size)
{
    const int b = blockIdx.x;
    const int c = threadIdx.x;

    __shared__ float ss[3][66];     // zero-padded ssim_info for this b
    __shared__ float gate[64];
    __shared__ float h1s[64];

#pragma unroll
    for (int j = 0; j < 3; ++j) {
        const float sj = g_ssim[(b*3 + j)*NC + c];
        ss[j][c + 1] = sj;
        if (out_size >= 2048) out[512 + b*NF*NC + j*NC + c] = sj;
        if (c == 0)  ss[j][0]  = 0.f;
        if (c == 63) ss[j][65] = 0.f;
    }
    __syncthreads();

    float g = 0.f;
#pragma unroll
    for (int j = 0; j < 3; ++j)
#pragma unroll
        for (int d = 0; d < 3; ++d)
            g = fmaf(sw[j*3 + d], ss[j][c + d], g);
    gate[c] = fmaxf(g, 0.f);
    __syncthreads();

    float h1 = b1[c];
#pragma unroll 8
    for (int k = 0; k < 64; ++k) h1 = fmaf(W1[c*64 + k], gate[k], h1);
    h1s[c] = fmaxf(h1, 0.f);
    __syncthreads();

    float h2 = b2[c];
#pragma unroll 8
    for (int k = 0; k < 64; ++k) h2 = fmaf(W2[c*64 + k], h1s[k], h2);
    out[b*64 + c] = 1.0f / (1.0f + expf(-h2));
}

// ---------------------------------------------------------------------------
extern "C" void kernel_launch(void* const* d_in, const int* in_sizes, int n_in,
                              void* d_out, int out_size)
{
    const float* x  = (const float*)d_in[0];
    const float* f  = (const float*)d_in[1];
    const float* sw = (const float*)d_in[2];
    const float* W1 = (const float*)d_in[3];
    const float* b1 = (const float*)d_in[4];
    const float* W2 = (const float*)d_in[5];
    const float* b2 = (const float*)d_in[6];
    float* out = (float*)d_out;

    zero_ssim_kernel<<<2, 768>>>();
    f_moments_kernel<<<dim3(14, 24), 192>>>(f);
    ssim_main_kernel<<<dim3(NB*NC, 2), 384>>>(x, f);
    epilogue_kernel<<<NB, 64>>>(sw, W1, b1, W2, b2, out, out_size);
}